// round 7
// baseline (speedup 1.0000x reference)
#include <cuda_runtime.h>
#include <math.h>

// GeodesicLoss: reference initializes velocity to zero, so the geodesic ODE
// acc = -Gamma v v is identically zero for all 10 steps -> traj == outputs.
// Result is exactly mean_b || outputs_b - targets_b ||_2.
// Pure streaming reduction over 128 MiB -> DRAM-bound.
//
// R7: R1's measured-best stream (block=256, grid=16384, one float4-pair per
// thread, 5.8 TB/s). Cross-block combine via fire-and-forget
// red.global.add.f32 into out[0] (NO return value -> blocks never wait on
// the LTS atomic queue, which is what collapsed R5/R6's stream to 50% DRAM).
// A 1-thread init kernel zeroes out[0] every replay (graph-edge ordered).

#define B_ROWS   524288
#define D_DIM    32
#define THREADS  256
#define NBLOCKS  16384       // NBLOCKS*THREADS = 4M threads = B_ROWS*8

__global__ void geodesic_init_kernel(float* __restrict__ out) {
    out[0] = 0.0f;
}

__global__ __launch_bounds__(THREADS)
void geodesic_loss_stream_kernel(const float* __restrict__ outputs,
                                 const float* __restrict__ targets,
                                 float* __restrict__ out) {
    const int tid = blockIdx.x * THREADS + threadIdx.x;
    const int row = tid >> 3;              // 8 lanes per row
    const int sub = threadIdx.x & 7;       // which float4 of the row

    const float4* __restrict__ o4 = reinterpret_cast<const float4*>(outputs);
    const float4* __restrict__ t4 = reinterpret_cast<const float4*>(targets);

    const int idx = row * (D_DIM / 4) + sub;
    float4 a = o4[idx];
    float4 b = t4[idx];

    float dx = a.x - b.x;
    float dy = a.y - b.y;
    float dz = a.z - b.z;
    float dw = a.w - b.w;
    float s = dx * dx + dy * dy + dz * dz + dw * dw;

    // Reduce the 8 lanes covering this row (butterfly)
    s += __shfl_xor_sync(0xFFFFFFFFu, s, 1);
    s += __shfl_xor_sync(0xFFFFFFFFu, s, 2);
    s += __shfl_xor_sync(0xFFFFFFFFu, s, 4);

    // One representative lane per row contributes sqrt(row_sum)
    float v = (sub == 0) ? sqrtf(s) : 0.0f;

    // Sum the 4 row-norms held in this warp (lanes 0,8,16,24)
    v += __shfl_xor_sync(0xFFFFFFFFu, v, 8);
    v += __shfl_xor_sync(0xFFFFFFFFu, v, 16);

    __shared__ float wsum[THREADS / 32];   // 8 warp sums
    if ((threadIdx.x & 31) == 0)
        wsum[threadIdx.x >> 5] = v;
    __syncthreads();

    if (threadIdx.x == 0) {
        float bsum = 0.0f;
        #pragma unroll
        for (int i = 0; i < THREADS / 32; i++)
            bsum += wsum[i];
        // Pre-scale by 1/B so out[0] accumulates the mean directly.
        bsum *= (1.0f / (float)B_ROWS);
        // Fire-and-forget reduction: no return value, no wait, block
        // retires immediately. REDG single-address throughput (~1.17/cyc)
        // is far above the ~0.75/us arrival rate when nothing blocks.
        asm volatile("red.global.add.f32 [%0], %1;"
                     :: "l"(out), "f"(bsum) : "memory");
    }
}

extern "C" void kernel_launch(void* const* d_in, const int* in_sizes, int n_in,
                              void* d_out, int out_size) {
    const float* outputs = (const float*)d_in[0];
    const float* targets = (const float*)d_in[1];
    // d_in[2] (christoffel_symbols) is mathematically dead: vel starts at 0.
    float* out = (float*)d_out;

    geodesic_init_kernel<<<1, 1>>>(out);
    geodesic_loss_stream_kernel<<<NBLOCKS, THREADS>>>(outputs, targets, out);
}

// round 8
// speedup vs baseline: 1.4742x; 1.4742x over previous
#include <cuda_runtime.h>
#include <math.h>

// GeodesicLoss: reference initializes velocity to zero, so the geodesic ODE
// acc = -Gamma v v is identically zero for all 10 steps -> traj == outputs.
// Result is exactly mean_b || outputs_b - targets_b ||_2.
// Pure streaming reduction over 128 MiB -> DRAM-bound.
//
// R8: lesson of R5-R7: ANY same-address atomic in the per-block tail taxes
// the stream (CTA exit waits on atomic commit; ~14 waves -> 10-20 DRAM pts).
// So: R1's tail-free stream (16384x256, one float4-pair/thread, plain STG
// partial -- the only config measured at ~22us) + a LEAN second reduce
// kernel (1024 thr, 4 independent float4 loads each, 1 barrier) replacing
// R1's 5.3us smem-tree version. __ldcs on stream loads (read-once data,
// evict-first in L2).

#define B_ROWS   524288
#define D_DIM    32
#define THREADS  256
#define NBLOCKS  16384       // NBLOCKS*THREADS = 4M threads = B_ROWS*8

__device__ float g_partials[NBLOCKS];

__global__ __launch_bounds__(THREADS)
void geodesic_loss_stream_kernel(const float* __restrict__ outputs,
                                 const float* __restrict__ targets) {
    const int tid = blockIdx.x * THREADS + threadIdx.x;
    const int row = tid >> 3;              // 8 lanes per row
    const int sub = threadIdx.x & 7;       // which float4 of the row

    const float4* __restrict__ o4 = reinterpret_cast<const float4*>(outputs);
    const float4* __restrict__ t4 = reinterpret_cast<const float4*>(targets);

    const int idx = row * (D_DIM / 4) + sub;
    float4 a = __ldcs(&o4[idx]);
    float4 b = __ldcs(&t4[idx]);

    float dx = a.x - b.x;
    float dy = a.y - b.y;
    float dz = a.z - b.z;
    float dw = a.w - b.w;
    float s = dx * dx + dy * dy + dz * dz + dw * dw;

    // Reduce the 8 lanes covering this row (butterfly)
    s += __shfl_xor_sync(0xFFFFFFFFu, s, 1);
    s += __shfl_xor_sync(0xFFFFFFFFu, s, 2);
    s += __shfl_xor_sync(0xFFFFFFFFu, s, 4);

    // One representative lane per row contributes sqrt(row_sum)
    float v = (sub == 0) ? sqrtf(s) : 0.0f;

    // Sum the 4 row-norms held in this warp (lanes 0,8,16,24)
    v += __shfl_xor_sync(0xFFFFFFFFu, v, 8);
    v += __shfl_xor_sync(0xFFFFFFFFu, v, 16);

    __shared__ float wsum[THREADS / 32];   // 8 warp sums
    if ((threadIdx.x & 31) == 0)
        wsum[threadIdx.x >> 5] = v;
    __syncthreads();

    if (threadIdx.x == 0) {
        float bsum = 0.0f;
        #pragma unroll
        for (int i = 0; i < THREADS / 32; i++)
            bsum += wsum[i];
        g_partials[blockIdx.x] = bsum;   // plain store: no CTA-exit atomic wait
    }
}

// Lean final reduce: 16384 partials = 4096 float4. 1024 threads x 4
// independent float4 loads (MLP=4), 5-shfl butterfly, ONE barrier.
// Fixed traversal order -> deterministic.
__global__ __launch_bounds__(1024)
void geodesic_final_reduce_kernel(float* __restrict__ out) {
    const float4* __restrict__ p4 = reinterpret_cast<const float4*>(g_partials);

    float4 v0 = p4[threadIdx.x];
    float4 v1 = p4[threadIdx.x + 1024];
    float4 v2 = p4[threadIdx.x + 2048];
    float4 v3 = p4[threadIdx.x + 3072];

    float s = ((v0.x + v0.y) + (v0.z + v0.w))
            + ((v1.x + v1.y) + (v1.z + v1.w))
            + ((v2.x + v2.y) + (v2.z + v2.w))
            + ((v3.x + v3.y) + (v3.z + v3.w));

    s += __shfl_xor_sync(0xFFFFFFFFu, s, 1);
    s += __shfl_xor_sync(0xFFFFFFFFu, s, 2);
    s += __shfl_xor_sync(0xFFFFFFFFu, s, 4);
    s += __shfl_xor_sync(0xFFFFFFFFu, s, 8);
    s += __shfl_xor_sync(0xFFFFFFFFu, s, 16);

    __shared__ float wsum[32];
    if ((threadIdx.x & 31) == 0)
        wsum[threadIdx.x >> 5] = s;
    __syncthreads();

    if (threadIdx.x < 32) {
        float t = wsum[threadIdx.x];
        t += __shfl_xor_sync(0xFFFFFFFFu, t, 1);
        t += __shfl_xor_sync(0xFFFFFFFFu, t, 2);
        t += __shfl_xor_sync(0xFFFFFFFFu, t, 4);
        t += __shfl_xor_sync(0xFFFFFFFFu, t, 8);
        t += __shfl_xor_sync(0xFFFFFFFFu, t, 16);
        if (threadIdx.x == 0)
            out[0] = t * (1.0f / (float)B_ROWS);
    }
}

extern "C" void kernel_launch(void* const* d_in, const int* in_sizes, int n_in,
                              void* d_out, int out_size) {
    const float* outputs = (const float*)d_in[0];
    const float* targets = (const float*)d_in[1];
    // d_in[2] (christoffel_symbols) is mathematically dead: vel starts at 0.
    float* out = (float*)d_out;

    geodesic_loss_stream_kernel<<<NBLOCKS, THREADS>>>(outputs, targets);
    geodesic_final_reduce_kernel<<<1, 1024>>>(out);
}